// round 14
// baseline (speedup 1.0000x reference)
#include <cuda_runtime.h>
#include <cstdint>

#define BB 2
#define SS 2048
#define EE 1024
#define HH 16
#define DHD 64
#define ME (4096 * 1024)
#define NE (1024 * 1024)

// ---------------------------------------------------------------------------
// PTX helpers (base-sm_103 features only)
// ---------------------------------------------------------------------------
__device__ __forceinline__ uint32_t smem_u32(const void* p) {
    uint32_t a;
    asm("{ .reg .u64 t; cvta.to.shared.u64 t, %1; cvt.u32.u64 %0, t; }" : "=r"(a) : "l"(p));
    return a;
}
__device__ __forceinline__ void ldsm4(uint32_t r[4], uint32_t a) {
    asm volatile("ldmatrix.sync.aligned.m8n8.x4.shared.b16 {%0,%1,%2,%3}, [%4];"
                 : "=r"(r[0]), "=r"(r[1]), "=r"(r[2]), "=r"(r[3]) : "r"(a));
}
__device__ __forceinline__ void ldsm4t(uint32_t r[4], uint32_t a) {
    asm volatile("ldmatrix.sync.aligned.m8n8.x4.trans.shared.b16 {%0,%1,%2,%3}, [%4];"
                 : "=r"(r[0]), "=r"(r[1]), "=r"(r[2]), "=r"(r[3]) : "r"(a));
}
__device__ __forceinline__ void mma_bf16(float d[4], const uint32_t a[4], const uint32_t b[2]) {
    asm volatile("mma.sync.aligned.m16n8k16.row.col.f32.bf16.bf16.f32 "
                 "{%0,%1,%2,%3}, {%4,%5,%6,%7}, {%8,%9}, {%0,%1,%2,%3};"
                 : "+f"(d[0]), "+f"(d[1]), "+f"(d[2]), "+f"(d[3])
                 : "r"(a[0]), "r"(a[1]), "r"(a[2]), "r"(a[3]), "r"(b[0]), "r"(b[1]));
}
// split fp32 pair -> bf16x2 hi + bf16x2 lo (x = hi + lo, exact residual)
__device__ __forceinline__ void split2(float2 v, uint32_t& hi, uint32_t& lo) {
    asm("cvt.rn.bf16x2.f32 %0, %1, %2;" : "=r"(hi) : "f"(v.y), "f"(v.x));
    float h0 = __uint_as_float(hi << 16);
    float h1 = __uint_as_float(hi & 0xFFFF0000u);
    asm("cvt.rn.bf16x2.f32 %0, %1, %2;" : "=r"(lo) : "f"(v.y - h1), "f"(v.x - h0));
}
__device__ __forceinline__ void cpa16(uint32_t dst, const void* src) {
    asm volatile("cp.async.cg.shared.global [%0], [%1], 16;" :: "r"(dst), "l"(src));
}
#define CPA_COMMIT() asm volatile("cp.async.commit_group;" ::: "memory")
#define CPA_WAIT0()  asm volatile("cp.async.wait_group 0;" ::: "memory")
#define CPA_WAIT1()  asm volatile("cp.async.wait_group 1;" ::: "memory")

// ---------------------------------------------------------------------------
// Global bf16 hi/lo scratch (allocation-free)
// ---------------------------------------------------------------------------
__device__ uint16_t g_ih[3 * ME], g_il[3 * ME];   // split inputs q,k,v
__device__ uint16_t g_wh[4 * NE], g_wl[4 * NE];   // split weights q,k,v,o
__device__ uint16_t g_ph[3 * ME], g_pl[3 * ME];   // projected Q,K,V (hi/lo)
__device__ uint16_t g_oh[ME],     g_ol[ME];       // attention output (hi/lo)

// ---------------------------------------------------------------------------
// Prep: fp32 -> bf16 hi/lo (inputs + weights in ONE launch; z selects tensor)
// ---------------------------------------------------------------------------
__global__ void split_all(const float* q, const float* k, const float* v,
                          const float* wq, const float* wk, const float* wv,
                          const float* wo,
                          uint16_t* ih, uint16_t* il,
                          uint16_t* wh, uint16_t* wl)
{
    const int z = blockIdx.y;
    const float2* sp;
    uint32_t *hp, *lp;
    int n;
    if (z < 3) {
        sp = (const float2*)(z == 0 ? q : z == 1 ? k : v);
        hp = (uint32_t*)(ih + (size_t)z * ME);
        lp = (uint32_t*)(il + (size_t)z * ME);
        n = ME / 2;
    } else {
        const int y = z - 3;
        sp = (const float2*)(y == 0 ? wq : y == 1 ? wk : y == 2 ? wv : wo);
        hp = (uint32_t*)(wh + (size_t)y * NE);
        lp = (uint32_t*)(wl + (size_t)y * NE);
        n = NE / 2;
    }
    for (int i = blockIdx.x * blockDim.x + threadIdx.x; i < n; i += gridDim.x * blockDim.x) {
        uint32_t h, l;
        split2(sp[i], h, l);
        hp[i] = h; lp[i] = l;
    }
}

// ---------------------------------------------------------------------------
// Projection GEMM: 128-thread CTAs, 4 CTAs/SM (independent-warp scheduling).
// Tile 128m x 64n, BK=64, 16 serial stages. Warp grid 2x2: each warp 64x32.
// smem: AHI[128][72] ALO BHI[64][72] BLO  (GP=72 pad, 144B rows) = 54 KB.
// ---------------------------------------------------------------------------
#define GP 72
#define GPB 144
#define P_AHI 0
#define P_ALO 18432
#define P_BHI 36864
#define P_BLO 46080
#define PRJ_SMEM 55296

__device__ __forceinline__ void gemm_body(
    const uint16_t* __restrict__ Ah, const uint16_t* __restrict__ Al,
    const uint16_t* __restrict__ Wh, const uint16_t* __restrict__ Wl,
    const float* __restrict__ bias, float scale, int mode,
    float* __restrict__ Cf, uint16_t* __restrict__ Ch, uint16_t* __restrict__ Cl,
    char* sm, int bm, int bn)
{
    const uint32_t smb = smem_u32(sm);
    const int tid = threadIdx.x;
    const int w = tid >> 5, lane = tid & 31;
    const int m0 = (w & 1) * 64, n0 = (w >> 1) * 32;
    const int r8 = lane & 7, quad = lane >> 3;
    const int arow = (quad & 1) * 8 + r8, acol = (quad >> 1) * 8;
    const int brow = (quad >> 1) * 8 + r8, bcol = (quad & 1) * 8;

    float acc[4][4][4];
#pragma unroll
    for (int i = 0; i < 4; i++)
#pragma unroll
        for (int j = 0; j < 4; j++)
#pragma unroll
            for (int k = 0; k < 4; k++) acc[i][j][k] = 0.0f;

    for (int s = 0; s < 16; s++) {
        const int kk0 = s << 6;
        __syncthreads();
        // copy: A 2048 chunks (2 arrays x 128 rows x 8), B 1024 (2 x 64 x 8)
#pragma unroll
        for (int it = 0; it < 24; it++) {
            int idx = tid + it * 128;              // 0..3071
            if (idx < 2048) {
                int a = idx >> 10, c = idx & 1023, row = c >> 3, cc = c & 7;
                const uint16_t* src = (a ? Al : Ah) + (size_t)(bm + row) * EE + kk0 + cc * 8;
                cpa16(smb + P_AHI + a * 18432 + row * GPB + cc * 16, src);
            } else {
                int i2 = idx - 2048;
                int a = i2 >> 9, c = i2 & 511, row = c >> 3, cc = c & 7;
                const uint16_t* src = (a ? Wl : Wh) + (size_t)(bn + row) * EE + kk0 + cc * 8;
                cpa16(smb + P_BHI + a * 9216 + row * GPB + cc * 16, src);
            }
        }
        CPA_COMMIT();
        CPA_WAIT0();
        __syncthreads();

#pragma unroll
        for (int kf = 0; kf < 4; kf++) {
            uint32_t bh[4][2], bl[4][2], t[4];
#pragma unroll
            for (int np = 0; np < 2; np++) {
                uint32_t boff = (uint32_t)((n0 + np * 16 + brow) * GP + kf * 16 + bcol) * 2;
                ldsm4(t, smb + P_BHI + boff);
                bh[np * 2][0] = t[0]; bh[np * 2][1] = t[1];
                bh[np * 2 + 1][0] = t[2]; bh[np * 2 + 1][1] = t[3];
                ldsm4(t, smb + P_BLO + boff);
                bl[np * 2][0] = t[0]; bl[np * 2][1] = t[1];
                bl[np * 2 + 1][0] = t[2]; bl[np * 2 + 1][1] = t[3];
            }
#pragma unroll
            for (int mf = 0; mf < 4; mf++) {
                uint32_t ah[4], al[4];
                uint32_t aoff = (uint32_t)((m0 + mf * 16 + arow) * GP + kf * 16 + acol) * 2;
                ldsm4(ah, smb + P_AHI + aoff);
                ldsm4(al, smb + P_ALO + aoff);
#pragma unroll
                for (int nf = 0; nf < 4; nf++) {
                    mma_bf16(acc[mf][nf], ah, bh[nf]);
                    mma_bf16(acc[mf][nf], ah, bl[nf]);
                    mma_bf16(acc[mf][nf], al, bh[nf]);
                }
            }
        }
    }

    const int g2 = lane >> 2, t2 = (lane & 3) * 2;
#pragma unroll
    for (int mf = 0; mf < 4; mf++)
#pragma unroll
        for (int nf = 0; nf < 4; nf++) {
            int row0 = bm + m0 + mf * 16 + g2;
            int col = bn + n0 + nf * 8 + t2;
            float b0 = bias[col], b1 = bias[col + 1];
            float v0 = (acc[mf][nf][0] + b0) * scale, v1 = (acc[mf][nf][1] + b1) * scale;
            float v2 = (acc[mf][nf][2] + b0) * scale, v3 = (acc[mf][nf][3] + b1) * scale;
            if (mode == 0) {
                *(float2*)(Cf + (size_t)row0 * EE + col) = make_float2(v0, v1);
                *(float2*)(Cf + (size_t)(row0 + 8) * EE + col) = make_float2(v2, v3);
            } else {
                uint32_t hi, lo;
                size_t off = (size_t)row0 * EE + col;
                split2(make_float2(v0, v1), hi, lo);
                *(uint32_t*)(Ch + off) = hi;
                *(uint32_t*)(Cl + off) = lo;
                split2(make_float2(v2, v3), hi, lo);
                off += (size_t)8 * EE;
                *(uint32_t*)(Ch + off) = hi;
                *(uint32_t*)(Cl + off) = lo;
            }
        }
}

__global__ __launch_bounds__(128, 4)
void gemm_qkv(const uint16_t* __restrict__ ih, const uint16_t* __restrict__ il,
              const uint16_t* __restrict__ wh, const uint16_t* __restrict__ wl,
              const float* __restrict__ bq, const float* __restrict__ bk,
              const float* __restrict__ bv,
              uint16_t* __restrict__ ph, uint16_t* __restrict__ pl)
{
    extern __shared__ char sm[];
    const int z = blockIdx.z;
    const float* bias = (z == 0) ? bq : (z == 1 ? bk : bv);
    gemm_body(ih + (size_t)z * ME, il + (size_t)z * ME,
              wh + (size_t)z * NE, wl + (size_t)z * NE,
              bias, (z == 0) ? 0.125f : 1.0f, 1,
              nullptr, ph + (size_t)z * ME, pl + (size_t)z * ME,
              sm, blockIdx.y * 128, blockIdx.x * 64);
}

__global__ __launch_bounds__(128, 4)
void gemm_o(const uint16_t* __restrict__ oh, const uint16_t* __restrict__ ol,
            const uint16_t* __restrict__ wh, const uint16_t* __restrict__ wl,
            const float* __restrict__ bo, float* __restrict__ out)
{
    extern __shared__ char sm[];
    gemm_body(oh, ol, wh, wl, bo, 1.0f, 0, out, nullptr, nullptr,
              sm, blockIdx.y * 128, blockIdx.x * 64);
}

// ---------------------------------------------------------------------------
// Fused attention (unchanged from R12): q-tile 64, k-tile 32, 128 threads,
// 4 CTAs/SM, three rotating K/V buffers, one barrier per iteration.
// ---------------------------------------------------------------------------
#define ATT_SMEM 55296

__device__ __forceinline__ void attn_issue_kv(
    uint32_t smb, int tid, uint32_t bufbase, size_t kb,
    const uint16_t* kh, const uint16_t* kl,
    const uint16_t* vh, const uint16_t* vl)
{
#pragma unroll
    for (int it = 0; it < 8; it++) {
        int idx = tid + it * 128;          // 0..1023
        int a = idx >> 8;                  // 0 KH, 1 KL, 2 VH, 3 VL (256 each)
        int c = idx & 255, row = c >> 3, cc = c & 7;
        const uint16_t* src =
            (a == 0 ? kh : a == 1 ? kl : a == 2 ? vh : vl) + kb + (size_t)row * EE + cc * 8;
        uint32_t dst = smb + bufbase + a * 4608 + row * GPB + cc * 16;
        cpa16(dst, src);
    }
}

__global__ __launch_bounds__(128, 4)
void attn_bf(const uint16_t* __restrict__ qh, const uint16_t* __restrict__ ql,
             const uint16_t* __restrict__ kh, const uint16_t* __restrict__ kl,
             const uint16_t* __restrict__ vh, const uint16_t* __restrict__ vl,
             const int* __restrict__ mask,
             uint16_t* __restrict__ oh, uint16_t* __restrict__ ol)
{
    extern __shared__ char sm[];
    const uint32_t smb = smem_u32(sm);
    const int tid = threadIdx.x;
    const int q0 = blockIdx.x * 64;
    const int bh = blockIdx.y, b = bh >> 4, h = bh & 15, hoff = h * DHD;
    const int w = tid >> 5, lane = tid & 31;
    const int r8 = lane & 7, quad = lane >> 3;
    const int arow = (quad & 1) * 8 + r8, acol = (quad >> 1) * 8;
    const int brow = (quad >> 1) * 8 + r8, bcol = (quad & 1) * 8;
    const int g = lane >> 2, t2 = (lane & 3) * 2;

    const size_t rowbase = (size_t)b * SS;
    const size_t qb = (rowbase + q0) * EE + hoff;

    // prologue: Q tile -> buffer 0 (hi @0, lo @9216); KV(0) -> buf1; KV(1) -> buf2
#pragma unroll
    for (int it = 0; it < 8; it++) {
        int idx = tid + it * 128;          // 0..1023
        int a = idx >> 9, c = idx & 511, row = c >> 3, cc = c & 7;
        const uint16_t* src = (a ? ql : qh) + qb + (size_t)row * EE + cc * 8;
        cpa16(smb + a * 9216 + row * GPB + cc * 16, src);
    }
    attn_issue_kv(smb, tid, 18432, rowbase * EE + hoff, kh, kl, vh, vl);
    CPA_COMMIT();                         // group0: Q + KV(0)
    attn_issue_kv(smb, tid, 36864, (rowbase + 32) * EE + hoff, kh, kl, vh, vl);
    CPA_COMMIT();                         // group1: KV(1)

    // wait group0 (Q + KV0), load Q fragments into registers permanently
    CPA_WAIT1();
    __syncthreads();
    uint32_t qfh[4][4], qfl[4][4];
#pragma unroll
    for (int kf = 0; kf < 4; kf++) {
        uint32_t aoff = (uint32_t)((w * 16 + arow) * GP + kf * 16 + acol) * 2;
        ldsm4(qfh[kf], smb + aoff);
        ldsm4(qfl[kf], smb + 9216 + aoff);
    }

    float acc2[8][4];
#pragma unroll
    for (int j = 0; j < 8; j++)
#pragma unroll
        for (int k = 0; k < 4; k++) acc2[j][k] = 0.0f;

    const int mrow0 = (int)(rowbase + q0 + w * 16 + g);

    int jb = 1;                            // buffer index of current stage: (s+1)%3
    for (int ht = 0; ht < 64; ht++) {
        const int kg0 = ht * 32;
        const uint32_t cb = (uint32_t)jb * 18432u;
        int pj = jb + 2; if (pj >= 3) pj -= 3;
        const uint32_t pb = (uint32_t)pj * 18432u;

        // mask prefetch FIRST — independent of the pending K/V stage
        int2 mA[4], mB[4];
#pragma unroll
        for (int j = 0; j < 4; j++) {
            const int* mp = mask + (size_t)mrow0 * SS + kg0 + j * 8 + t2;
            mA[j] = *(const int2*)mp;
            mB[j] = *(const int2*)(mp + (size_t)8 * SS);
        }

        CPA_WAIT1();                       // KV(ht) complete (KV(ht+1) may be in flight)
        __syncthreads();                   // (a) data visible (b) compute(ht-1) done -> pb free

        if (ht + 2 < 64)
            attn_issue_kv(smb, tid, pb, (rowbase + (ht + 2) * 32) * EE + hoff, kh, kl, vh, vl);
        CPA_COMMIT();

        const uint32_t khs = smb + cb,        kls = khs + 4608;
        const uint32_t vhs = smb + cb + 9216, vls = vhs + 4608;

        // gemm1: S[16,32] = Q[16,64] * Khalf[32,64]^T  (Q pre-scaled by 1/8)
        float acc1[4][4];
#pragma unroll
        for (int j = 0; j < 4; j++)
#pragma unroll
            for (int k = 0; k < 4; k++) acc1[j][k] = 0.0f;

#pragma unroll
        for (int kf = 0; kf < 4; kf++) {
            uint32_t bhf[4][2], blf[4][2], t[4];
#pragma unroll
            for (int np = 0; np < 2; np++) {
                uint32_t boff = (uint32_t)((np * 16 + brow) * GP + kf * 16 + bcol) * 2;
                ldsm4(t, khs + boff);
                bhf[np * 2][0] = t[0]; bhf[np * 2][1] = t[1];
                bhf[np * 2 + 1][0] = t[2]; bhf[np * 2 + 1][1] = t[3];
                ldsm4(t, kls + boff);
                blf[np * 2][0] = t[0]; blf[np * 2][1] = t[1];
                blf[np * 2 + 1][0] = t[2]; blf[np * 2 + 1][1] = t[3];
            }
#pragma unroll
            for (int nf = 0; nf < 4; nf++) {
                mma_bf16(acc1[nf], qfh[kf], bhf[nf]);
                mma_bf16(acc1[nf], qfh[kf], blf[nf]);
                mma_bf16(acc1[nf], qfl[kf], bhf[nf]);
            }
        }

        // mask in-register, split to S fragments (A-operand layout, k-dim 32)
        uint32_t sfh[2][4], sfl[2][4];
#pragma unroll
        for (int j = 0; j < 4; j++) {
            float v0 = mA[j].x ? acc1[j][0] : 1e-9f;
            float v1 = mA[j].y ? acc1[j][1] : 1e-9f;
            float v2 = mB[j].x ? acc1[j][2] : 1e-9f;
            float v3 = mB[j].y ? acc1[j][3] : 1e-9f;
            int kf = j >> 1, hi2 = (j & 1) * 2;
            split2(make_float2(v0, v1), sfh[kf][hi2], sfl[kf][hi2]);
            split2(make_float2(v2, v3), sfh[kf][hi2 + 1], sfl[kf][hi2 + 1]);
        }

        // gemm2: O[16,64] += S[16,32] * Vhalf[32,64]
#pragma unroll
        for (int kf = 0; kf < 2; kf++) {
            uint32_t bhf[8][2], blf[8][2], t[4];
#pragma unroll
            for (int dp = 0; dp < 4; dp++) {
                uint32_t voff = (uint32_t)((kf * 16 + (quad & 1) * 8 + r8) * GP +
                                           dp * 16 + (quad >> 1) * 8) * 2;
                ldsm4t(t, vhs + voff);
                bhf[dp * 2][0] = t[0]; bhf[dp * 2][1] = t[1];
                bhf[dp * 2 + 1][0] = t[2]; bhf[dp * 2 + 1][1] = t[3];
                ldsm4t(t, vls + voff);
                blf[dp * 2][0] = t[0]; blf[dp * 2][1] = t[1];
                blf[dp * 2 + 1][0] = t[2]; blf[dp * 2 + 1][1] = t[3];
            }
#pragma unroll
            for (int nf = 0; nf < 8; nf++) {
                mma_bf16(acc2[nf], sfh[kf], bhf[nf]);
                mma_bf16(acc2[nf], sfh[kf], blf[nf]);
                mma_bf16(acc2[nf], sfl[kf], bhf[nf]);
            }
        }
        // NO trailing barrier — next iteration's single sync guards the rotation.
        jb++; if (jb == 3) jb = 0;
    }

    // epilogue: split O to hi/lo bf16
#pragma unroll
    for (int j = 0; j < 8; j++) {
        int col = hoff + j * 8 + t2;
        size_t off = (size_t)mrow0 * EE + col;
        uint32_t hi, lo;
        split2(make_float2(acc2[j][0], acc2[j][1]), hi, lo);
        *(uint32_t*)(oh + off) = hi;
        *(uint32_t*)(ol + off) = lo;
        split2(make_float2(acc2[j][2], acc2[j][3]), hi, lo);
        off += (size_t)8 * EE;
        *(uint32_t*)(oh + off) = hi;
        *(uint32_t*)(ol + off) = lo;
    }
}

// ---------------------------------------------------------------------------
extern "C" void kernel_launch(void* const* d_in, const int* in_sizes, int n_in,
                              void* d_out, int out_size)
{
    const float* query = (const float*)d_in[0];
    const float* key   = (const float*)d_in[1];
    const float* value = (const float*)d_in[2];
    const int*   mask  = (const int*)  d_in[3];
    const float* Wq    = (const float*)d_in[4];
    const float* bq    = (const float*)d_in[5];
    const float* Wk    = (const float*)d_in[6];
    const float* bk    = (const float*)d_in[7];
    const float* Wv    = (const float*)d_in[8];
    const float* bv    = (const float*)d_in[9];
    const float* Wo    = (const float*)d_in[10];
    const float* bo    = (const float*)d_in[11];
    float* out = (float*)d_out;

    uint16_t *ih, *il, *wh, *wl, *ph, *pl, *oh, *ol;
    cudaGetSymbolAddress((void**)&ih, g_ih);
    cudaGetSymbolAddress((void**)&il, g_il);
    cudaGetSymbolAddress((void**)&wh, g_wh);
    cudaGetSymbolAddress((void**)&wl, g_wl);
    cudaGetSymbolAddress((void**)&ph, g_ph);
    cudaGetSymbolAddress((void**)&pl, g_pl);
    cudaGetSymbolAddress((void**)&oh, g_oh);
    cudaGetSymbolAddress((void**)&ol, g_ol);

    cudaFuncSetAttribute(gemm_qkv, cudaFuncAttributeMaxDynamicSharedMemorySize, PRJ_SMEM);
    cudaFuncSetAttribute(gemm_o,   cudaFuncAttributeMaxDynamicSharedMemorySize, PRJ_SMEM);
    cudaFuncSetAttribute(attn_bf,  cudaFuncAttributeMaxDynamicSharedMemorySize, ATT_SMEM);

    split_all<<<dim3(384, 7), 256>>>(query, key, value, Wq, Wk, Wv, Wo, ih, il, wh, wl);

    dim3 qkvgrid(EE / 64, (BB * SS) / 128, 3);   // (16, 32, 3) = 1536 CTAs
    gemm_qkv<<<qkvgrid, 128, PRJ_SMEM>>>(ih, il, wh, wl, bq, bk, bv, ph, pl);

    dim3 agrid(SS / 64, BB * HH);   // (32, 32) = 1024 CTAs, 4 per SM
    attn_bf<<<agrid, 128, ATT_SMEM>>>(ph, pl, ph + ME, pl + ME, ph + 2 * ME, pl + 2 * ME,
                                      mask, oh, ol);

    dim3 ogrid(EE / 64, (BB * SS) / 128);   // (16, 32)
    gemm_o<<<ogrid, 128, PRJ_SMEM>>>(oh, ol, wh + 3 * NE, wl + 3 * NE, bo, out);
}

// round 15
// speedup vs baseline: 1.0778x; 1.0778x over previous
#include <cuda_runtime.h>
#include <cstdint>

#define BB 2
#define SS 2048
#define EE 1024
#define HH 16
#define DHD 64
#define ME (4096 * 1024)
#define NE (1024 * 1024)

// ---------------------------------------------------------------------------
// PTX helpers (base-sm_103 features only)
// ---------------------------------------------------------------------------
__device__ __forceinline__ uint32_t smem_u32(const void* p) {
    uint32_t a;
    asm("{ .reg .u64 t; cvta.to.shared.u64 t, %1; cvt.u32.u64 %0, t; }" : "=r"(a) : "l"(p));
    return a;
}
__device__ __forceinline__ void ldsm4(uint32_t r[4], uint32_t a) {
    asm volatile("ldmatrix.sync.aligned.m8n8.x4.shared.b16 {%0,%1,%2,%3}, [%4];"
                 : "=r"(r[0]), "=r"(r[1]), "=r"(r[2]), "=r"(r[3]) : "r"(a));
}
__device__ __forceinline__ void ldsm4t(uint32_t r[4], uint32_t a) {
    asm volatile("ldmatrix.sync.aligned.m8n8.x4.trans.shared.b16 {%0,%1,%2,%3}, [%4];"
                 : "=r"(r[0]), "=r"(r[1]), "=r"(r[2]), "=r"(r[3]) : "r"(a));
}
__device__ __forceinline__ void mma_bf16(float d[4], const uint32_t a[4], const uint32_t b[2]) {
    asm volatile("mma.sync.aligned.m16n8k16.row.col.f32.bf16.bf16.f32 "
                 "{%0,%1,%2,%3}, {%4,%5,%6,%7}, {%8,%9}, {%0,%1,%2,%3};"
                 : "+f"(d[0]), "+f"(d[1]), "+f"(d[2]), "+f"(d[3])
                 : "r"(a[0]), "r"(a[1]), "r"(a[2]), "r"(a[3]), "r"(b[0]), "r"(b[1]));
}
__device__ __forceinline__ void mma_f16(float d[4], const uint32_t a[4], const uint32_t b[2]) {
    asm volatile("mma.sync.aligned.m16n8k16.row.col.f32.f16.f16.f32 "
                 "{%0,%1,%2,%3}, {%4,%5,%6,%7}, {%8,%9}, {%0,%1,%2,%3};"
                 : "+f"(d[0]), "+f"(d[1]), "+f"(d[2]), "+f"(d[3])
                 : "r"(a[0]), "r"(a[1]), "r"(a[2]), "r"(a[3]), "r"(b[0]), "r"(b[1]));
}
// split fp32 pair -> bf16x2 hi + bf16x2 lo (x = hi + lo, exact residual)
__device__ __forceinline__ void split2(float2 v, uint32_t& hi, uint32_t& lo) {
    asm("cvt.rn.bf16x2.f32 %0, %1, %2;" : "=r"(hi) : "f"(v.y), "f"(v.x));
    float h0 = __uint_as_float(hi << 16);
    float h1 = __uint_as_float(hi & 0xFFFF0000u);
    asm("cvt.rn.bf16x2.f32 %0, %1, %2;" : "=r"(lo) : "f"(v.y - h1), "f"(v.x - h0));
}
// split fp32 pair -> fp16x2 hi + fp16x2 lo (x = hi + lo, residual ~u^2)
__device__ __forceinline__ void split2h(float2 v, uint32_t& hi, uint32_t& lo) {
    asm("cvt.rn.f16x2.f32 %0, %1, %2;" : "=r"(hi) : "f"(v.y), "f"(v.x));
    float h0, h1;
    asm("{\n\t.reg .f16 a, b;\n\tmov.b32 {a, b}, %2;\n\t"
        "cvt.f32.f16 %0, a;\n\tcvt.f32.f16 %1, b;\n\t}"
        : "=f"(h0), "=f"(h1) : "r"(hi));
    asm("cvt.rn.f16x2.f32 %0, %1, %2;" : "=r"(lo) : "f"(v.y - h1), "f"(v.x - h0));
}
__device__ __forceinline__ void cpa16(uint32_t dst, const void* src) {
    asm volatile("cp.async.cg.shared.global [%0], [%1], 16;" :: "r"(dst), "l"(src));
}
#define CPA_COMMIT() asm volatile("cp.async.commit_group;" ::: "memory")
#define CPA_WAIT0()  asm volatile("cp.async.wait_group 0;" ::: "memory")
#define CPA_WAIT1()  asm volatile("cp.async.wait_group 1;" ::: "memory")

// ---------------------------------------------------------------------------
// Global bf16/fp16 hi/lo scratch (allocation-free)
// ---------------------------------------------------------------------------
__device__ uint16_t g_ih[3 * ME], g_il[3 * ME];   // split inputs q,k,v (bf16)
__device__ uint16_t g_wh[4 * NE], g_wl[4 * NE];   // split weights (bf16)
__device__ uint16_t g_ph[3 * ME], g_pl[3 * ME];   // projected Q,K (bf16) / V (fp16)
__device__ uint16_t g_oh[ME],     g_ol[ME];       // attention output (bf16)

// ---------------------------------------------------------------------------
// Prep: fp32 -> bf16 hi/lo (inputs + weights in ONE launch; z selects tensor)
// ---------------------------------------------------------------------------
__global__ void split_all(const float* q, const float* k, const float* v,
                          const float* wq, const float* wk, const float* wv,
                          const float* wo,
                          uint16_t* ih, uint16_t* il,
                          uint16_t* wh, uint16_t* wl)
{
    const int z = blockIdx.y;
    const float2* sp;
    uint32_t *hp, *lp;
    int n;
    if (z < 3) {
        sp = (const float2*)(z == 0 ? q : z == 1 ? k : v);
        hp = (uint32_t*)(ih + (size_t)z * ME);
        lp = (uint32_t*)(il + (size_t)z * ME);
        n = ME / 2;
    } else {
        const int y = z - 3;
        sp = (const float2*)(y == 0 ? wq : y == 1 ? wk : y == 2 ? wv : wo);
        hp = (uint32_t*)(wh + (size_t)y * NE);
        lp = (uint32_t*)(wl + (size_t)y * NE);
        n = NE / 2;
    }
    for (int i = blockIdx.x * blockDim.x + threadIdx.x; i < n; i += gridDim.x * blockDim.x) {
        uint32_t h, l;
        split2(sp[i], h, l);
        hp[i] = h; lp[i] = l;
    }
}

// ---------------------------------------------------------------------------
// Projection GEMM body — EXACT R12 champion structure (BK=64, 16 serial
// stages, 256 threads, occ 2). mode 0: fp32 out; 1: bf16 hi/lo; 2: fp16 hi/lo.
// ---------------------------------------------------------------------------
#define GP 72
#define GPB 144
#define O_AHI 0
#define O_ALO 18432
#define O_BHI 36864
#define O_BLO 55296
#define PRJ_SMEM 73728

__device__ __forceinline__ void gemm_body(
    const uint16_t* __restrict__ Ah, const uint16_t* __restrict__ Al,
    const uint16_t* __restrict__ Wh, const uint16_t* __restrict__ Wl,
    const float* __restrict__ bias, float scale, int mode,
    float* __restrict__ Cf, uint16_t* __restrict__ Ch, uint16_t* __restrict__ Cl,
    char* sm, int bm, int bn)
{
    const uint32_t smb = smem_u32(sm);
    const int tid = threadIdx.x;
    const int w = tid >> 5, lane = tid & 31;
    const int m0 = (w & 1) * 64, n0 = (w >> 1) * 32;
    const int r8 = lane & 7, quad = lane >> 3;
    const int arow = (quad & 1) * 8 + r8, acol = (quad >> 1) * 8;
    const int brow = (quad >> 1) * 8 + r8, bcol = (quad & 1) * 8;

    float acc[4][4][4];
#pragma unroll
    for (int i = 0; i < 4; i++)
#pragma unroll
        for (int j = 0; j < 4; j++)
#pragma unroll
            for (int k = 0; k < 4; k++) acc[i][j][k] = 0.0f;

    for (int s = 0; s < 16; s++) {
        const int kk0 = s << 6;
        __syncthreads();
#pragma unroll
        for (int it = 0; it < 16; it++) {
            int idx = tid + it * 256;
            int a = idx >> 10, c = idx & 1023, row = c >> 3, cc = c & 7;
            const uint16_t* src;
            if (a == 0)      src = Ah + (size_t)(bm + row) * EE + kk0;
            else if (a == 1) src = Al + (size_t)(bm + row) * EE + kk0;
            else if (a == 2) src = Wh + (size_t)(bn + row) * EE + kk0;
            else             src = Wl + (size_t)(bn + row) * EE + kk0;
            cpa16(smb + a * 18432 + row * GPB + cc * 16, src + cc * 8);
        }
        CPA_COMMIT();
        CPA_WAIT0();
        __syncthreads();

#pragma unroll
        for (int kf = 0; kf < 4; kf++) {
            uint32_t bh[4][2], bl[4][2], t[4];
#pragma unroll
            for (int np = 0; np < 2; np++) {
                uint32_t boff = (uint32_t)((n0 + np * 16 + brow) * GP + kf * 16 + bcol) * 2;
                ldsm4(t, smb + O_BHI + boff);
                bh[np * 2][0] = t[0]; bh[np * 2][1] = t[1];
                bh[np * 2 + 1][0] = t[2]; bh[np * 2 + 1][1] = t[3];
                ldsm4(t, smb + O_BLO + boff);
                bl[np * 2][0] = t[0]; bl[np * 2][1] = t[1];
                bl[np * 2 + 1][0] = t[2]; bl[np * 2 + 1][1] = t[3];
            }
#pragma unroll
            for (int mf = 0; mf < 4; mf++) {
                uint32_t ah[4], al[4];
                uint32_t aoff = (uint32_t)((m0 + mf * 16 + arow) * GP + kf * 16 + acol) * 2;
                ldsm4(ah, smb + O_AHI + aoff);
                ldsm4(al, smb + O_ALO + aoff);
#pragma unroll
                for (int nf = 0; nf < 4; nf++) {
                    mma_bf16(acc[mf][nf], ah, bh[nf]);
                    mma_bf16(acc[mf][nf], ah, bl[nf]);
                    mma_bf16(acc[mf][nf], al, bh[nf]);
                }
            }
        }
    }

    const int g2 = lane >> 2, t2 = (lane & 3) * 2;
#pragma unroll
    for (int mf = 0; mf < 4; mf++)
#pragma unroll
        for (int nf = 0; nf < 4; nf++) {
            int row0 = bm + m0 + mf * 16 + g2;
            int col = bn + n0 + nf * 8 + t2;
            float b0 = bias[col], b1 = bias[col + 1];
            float v0 = (acc[mf][nf][0] + b0) * scale, v1 = (acc[mf][nf][1] + b1) * scale;
            float v2 = (acc[mf][nf][2] + b0) * scale, v3 = (acc[mf][nf][3] + b1) * scale;
            if (mode == 0) {
                *(float2*)(Cf + (size_t)row0 * EE + col) = make_float2(v0, v1);
                *(float2*)(Cf + (size_t)(row0 + 8) * EE + col) = make_float2(v2, v3);
            } else if (mode == 1) {
                uint32_t hi, lo;
                size_t off = (size_t)row0 * EE + col;
                split2(make_float2(v0, v1), hi, lo);
                *(uint32_t*)(Ch + off) = hi;
                *(uint32_t*)(Cl + off) = lo;
                split2(make_float2(v2, v3), hi, lo);
                off += (size_t)8 * EE;
                *(uint32_t*)(Ch + off) = hi;
                *(uint32_t*)(Cl + off) = lo;
            } else {
                uint32_t hi, lo;
                size_t off = (size_t)row0 * EE + col;
                split2h(make_float2(v0, v1), hi, lo);
                *(uint32_t*)(Ch + off) = hi;
                *(uint32_t*)(Cl + off) = lo;
                split2h(make_float2(v2, v3), hi, lo);
                off += (size_t)8 * EE;
                *(uint32_t*)(Ch + off) = hi;
                *(uint32_t*)(Cl + off) = lo;
            }
        }
}

__global__ __launch_bounds__(256, 2)
void gemm_qkv(const uint16_t* __restrict__ ih, const uint16_t* __restrict__ il,
              const uint16_t* __restrict__ wh, const uint16_t* __restrict__ wl,
              const float* __restrict__ bq, const float* __restrict__ bk,
              const float* __restrict__ bv,
              uint16_t* __restrict__ ph, uint16_t* __restrict__ pl)
{
    extern __shared__ char sm[];
    const int z = blockIdx.z;
    const float* bias = (z == 0) ? bq : (z == 1 ? bk : bv);
    gemm_body(ih + (size_t)z * ME, il + (size_t)z * ME,
              wh + (size_t)z * NE, wl + (size_t)z * NE,
              bias, (z == 0) ? 0.125f : 1.0f, (z == 2) ? 2 : 1,
              nullptr, ph + (size_t)z * ME, pl + (size_t)z * ME,
              sm, blockIdx.y * 128, blockIdx.x * 128);
}

__global__ __launch_bounds__(256, 2)
void gemm_o(const uint16_t* __restrict__ oh, const uint16_t* __restrict__ ol,
            const uint16_t* __restrict__ wh, const uint16_t* __restrict__ wl,
            const float* __restrict__ bo, float* __restrict__ out)
{
    extern __shared__ char sm[];
    gemm_body(oh, ol, wh, wl, bo, 1.0f, 0, out, nullptr, nullptr,
              sm, blockIdx.y * 128, blockIdx.x * 128);
}

// ---------------------------------------------------------------------------
// Fused attention (R12 structure): q-tile 64, k-tile 32, 128 threads,
// 4 CTAs/SM, three rotating K/V buffers, one barrier per iteration.
// gemm1: bf16 3-term (Q/K bf16-split). gemm2: fp16 2-term (S single fp16,
// V fp16-split). Q pre-scaled by 1/8.
// ---------------------------------------------------------------------------
#define ATT_SMEM 55296

__device__ __forceinline__ void attn_issue_kv(
    uint32_t smb, int tid, uint32_t bufbase, size_t kb,
    const uint16_t* kh, const uint16_t* kl,
    const uint16_t* vh, const uint16_t* vl)
{
#pragma unroll
    for (int it = 0; it < 8; it++) {
        int idx = tid + it * 128;          // 0..1023
        int a = idx >> 8;                  // 0 KH, 1 KL, 2 VH, 3 VL (256 each)
        int c = idx & 255, row = c >> 3, cc = c & 7;
        const uint16_t* src =
            (a == 0 ? kh : a == 1 ? kl : a == 2 ? vh : vl) + kb + (size_t)row * EE + cc * 8;
        uint32_t dst = smb + bufbase + a * 4608 + row * GPB + cc * 16;
        cpa16(dst, src);
    }
}

__global__ __launch_bounds__(128, 4)
void attn_bf(const uint16_t* __restrict__ qh, const uint16_t* __restrict__ ql,
             const uint16_t* __restrict__ kh, const uint16_t* __restrict__ kl,
             const uint16_t* __restrict__ vh, const uint16_t* __restrict__ vl,
             const int* __restrict__ mask,
             uint16_t* __restrict__ oh, uint16_t* __restrict__ ol)
{
    extern __shared__ char sm[];
    const uint32_t smb = smem_u32(sm);
    const int tid = threadIdx.x;
    const int q0 = blockIdx.x * 64;
    const int bh = blockIdx.y, b = bh >> 4, h = bh & 15, hoff = h * DHD;
    const int w = tid >> 5, lane = tid & 31;
    const int r8 = lane & 7, quad = lane >> 3;
    const int arow = (quad & 1) * 8 + r8, acol = (quad >> 1) * 8;
    const int brow = (quad >> 1) * 8 + r8, bcol = (quad & 1) * 8;
    const int g = lane >> 2, t2 = (lane & 3) * 2;

    const size_t rowbase = (size_t)b * SS;
    const size_t qb = (rowbase + q0) * EE + hoff;

    // prologue: Q tile -> buffer 0 (hi @0, lo @9216); KV(0) -> buf1; KV(1) -> buf2
#pragma unroll
    for (int it = 0; it < 8; it++) {
        int idx = tid + it * 128;          // 0..1023
        int a = idx >> 9, c = idx & 511, row = c >> 3, cc = c & 7;
        const uint16_t* src = (a ? ql : qh) + qb + (size_t)row * EE + cc * 8;
        cpa16(smb + a * 9216 + row * GPB + cc * 16, src);
    }
    attn_issue_kv(smb, tid, 18432, rowbase * EE + hoff, kh, kl, vh, vl);
    CPA_COMMIT();                         // group0: Q + KV(0)
    attn_issue_kv(smb, tid, 36864, (rowbase + 32) * EE + hoff, kh, kl, vh, vl);
    CPA_COMMIT();                         // group1: KV(1)

    // wait group0 (Q + KV0), load Q fragments into registers permanently
    CPA_WAIT1();
    __syncthreads();
    uint32_t qfh[4][4], qfl[4][4];
#pragma unroll
    for (int kf = 0; kf < 4; kf++) {
        uint32_t aoff = (uint32_t)((w * 16 + arow) * GP + kf * 16 + acol) * 2;
        ldsm4(qfh[kf], smb + aoff);
        ldsm4(qfl[kf], smb + 9216 + aoff);
    }

    float acc2[8][4];
#pragma unroll
    for (int j = 0; j < 8; j++)
#pragma unroll
        for (int k = 0; k < 4; k++) acc2[j][k] = 0.0f;

    const int mrow0 = (int)(rowbase + q0 + w * 16 + g);

    int jb = 1;                            // buffer index of current stage: (s+1)%3
    for (int ht = 0; ht < 64; ht++) {
        const int kg0 = ht * 32;
        const uint32_t cb = (uint32_t)jb * 18432u;
        int pj = jb + 2; if (pj >= 3) pj -= 3;
        const uint32_t pb = (uint32_t)pj * 18432u;

        // mask prefetch FIRST — independent of the pending K/V stage
        int2 mA[4], mB[4];
#pragma unroll
        for (int j = 0; j < 4; j++) {
            const int* mp = mask + (size_t)mrow0 * SS + kg0 + j * 8 + t2;
            mA[j] = *(const int2*)mp;
            mB[j] = *(const int2*)(mp + (size_t)8 * SS);
        }

        CPA_WAIT1();                       // KV(ht) complete (KV(ht+1) may be in flight)
        __syncthreads();                   // (a) data visible (b) compute(ht-1) done -> pb free

        if (ht + 2 < 64)
            attn_issue_kv(smb, tid, pb, (rowbase + (ht + 2) * 32) * EE + hoff, kh, kl, vh, vl);
        CPA_COMMIT();

        const uint32_t khs = smb + cb,        kls = khs + 4608;
        const uint32_t vhs = smb + cb + 9216, vls = vhs + 4608;

        // gemm1: S[16,32] = Q[16,64] * Khalf[32,64]^T  (Q pre-scaled by 1/8)
        float acc1[4][4];
#pragma unroll
        for (int j = 0; j < 4; j++)
#pragma unroll
            for (int k = 0; k < 4; k++) acc1[j][k] = 0.0f;

#pragma unroll
        for (int kf = 0; kf < 4; kf++) {
            uint32_t bhf[4][2], blf[4][2], t[4];
#pragma unroll
            for (int np = 0; np < 2; np++) {
                uint32_t boff = (uint32_t)((np * 16 + brow) * GP + kf * 16 + bcol) * 2;
                ldsm4(t, khs + boff);
                bhf[np * 2][0] = t[0]; bhf[np * 2][1] = t[1];
                bhf[np * 2 + 1][0] = t[2]; bhf[np * 2 + 1][1] = t[3];
                ldsm4(t, kls + boff);
                blf[np * 2][0] = t[0]; blf[np * 2][1] = t[1];
                blf[np * 2 + 1][0] = t[2]; blf[np * 2 + 1][1] = t[3];
            }
#pragma unroll
            for (int nf = 0; nf < 4; nf++) {
                mma_bf16(acc1[nf], qfh[kf], bhf[nf]);
                mma_bf16(acc1[nf], qfh[kf], blf[nf]);
                mma_bf16(acc1[nf], qfl[kf], bhf[nf]);
            }
        }

        // mask in-register, convert S to single fp16 A-fragments
        uint32_t sf[2][4];
#pragma unroll
        for (int j = 0; j < 4; j++) {
            float v0 = mA[j].x ? acc1[j][0] : 1e-9f;
            float v1 = mA[j].y ? acc1[j][1] : 1e-9f;
            float v2 = mB[j].x ? acc1[j][2] : 1e-9f;
            float v3 = mB[j].y ? acc1[j][3] : 1e-9f;
            int kf = j >> 1, hi2 = (j & 1) * 2;
            asm("cvt.rn.f16x2.f32 %0, %1, %2;" : "=r"(sf[kf][hi2])     : "f"(v1), "f"(v0));
            asm("cvt.rn.f16x2.f32 %0, %1, %2;" : "=r"(sf[kf][hi2 + 1]) : "f"(v3), "f"(v2));
        }

        // gemm2: O[16,64] += S[16,32] * Vhalf[32,64]   (fp16 2-term)
#pragma unroll
        for (int kf = 0; kf < 2; kf++) {
            uint32_t bhf[8][2], blf[8][2], t[4];
#pragma unroll
            for (int dp = 0; dp < 4; dp++) {
                uint32_t voff = (uint32_t)((kf * 16 + (quad & 1) * 8 + r8) * GP +
                                           dp * 16 + (quad >> 1) * 8) * 2;
                ldsm4t(t, vhs + voff);
                bhf[dp * 2][0] = t[0]; bhf[dp * 2][1] = t[1];
                bhf[dp * 2 + 1][0] = t[2]; bhf[dp * 2 + 1][1] = t[3];
                ldsm4t(t, vls + voff);
                blf[dp * 2][0] = t[0]; blf[dp * 2][1] = t[1];
                blf[dp * 2 + 1][0] = t[2]; blf[dp * 2 + 1][1] = t[3];
            }
#pragma unroll
            for (int nf = 0; nf < 8; nf++) {
                mma_f16(acc2[nf], sf[kf], bhf[nf]);
                mma_f16(acc2[nf], sf[kf], blf[nf]);
            }
        }
        // NO trailing barrier — next iteration's single sync guards the rotation.
        jb++; if (jb == 3) jb = 0;
    }

    // epilogue: split O to hi/lo bf16
#pragma unroll
    for (int j = 0; j < 8; j++) {
        int col = hoff + j * 8 + t2;
        size_t off = (size_t)mrow0 * EE + col;
        uint32_t hi, lo;
        split2(make_float2(acc2[j][0], acc2[j][1]), hi, lo);
        *(uint32_t*)(oh + off) = hi;
        *(uint32_t*)(ol + off) = lo;
        split2(make_float2(acc2[j][2], acc2[j][3]), hi, lo);
        off += (size_t)8 * EE;
        *(uint32_t*)(oh + off) = hi;
        *(uint32_t*)(ol + off) = lo;
    }
}

// ---------------------------------------------------------------------------
extern "C" void kernel_launch(void* const* d_in, const int* in_sizes, int n_in,
                              void* d_out, int out_size)
{
    const float* query = (const float*)d_in[0];
    const float* key   = (const float*)d_in[1];
    const float* value = (const float*)d_in[2];
    const int*   mask  = (const int*)  d_in[3];
    const float* Wq    = (const float*)d_in[4];
    const float* bq    = (const float*)d_in[5];
    const float* Wk    = (const float*)d_in[6];
    const float* bk    = (const float*)d_in[7];
    const float* Wv    = (const float*)d_in[8];
    const float* bv    = (const float*)d_in[9];
    const float* Wo    = (const float*)d_in[10];
    const float* bo    = (const float*)d_in[11];
    float* out = (float*)d_out;

    uint16_t *ih, *il, *wh, *wl, *ph, *pl, *oh, *ol;
    cudaGetSymbolAddress((void**)&ih, g_ih);
    cudaGetSymbolAddress((void**)&il, g_il);
    cudaGetSymbolAddress((void**)&wh, g_wh);
    cudaGetSymbolAddress((void**)&wl, g_wl);
    cudaGetSymbolAddress((void**)&ph, g_ph);
    cudaGetSymbolAddress((void**)&pl, g_pl);
    cudaGetSymbolAddress((void**)&oh, g_oh);
    cudaGetSymbolAddress((void**)&ol, g_ol);

    cudaFuncSetAttribute(gemm_qkv, cudaFuncAttributeMaxDynamicSharedMemorySize, PRJ_SMEM);
    cudaFuncSetAttribute(gemm_o,   cudaFuncAttributeMaxDynamicSharedMemorySize, PRJ_SMEM);
    cudaFuncSetAttribute(attn_bf,  cudaFuncAttributeMaxDynamicSharedMemorySize, ATT_SMEM);

    split_all<<<dim3(384, 7), 256>>>(query, key, value, Wq, Wk, Wv, Wo, ih, il, wh, wl);

    dim3 qkvgrid(EE / 128, (BB * SS) / 128, 3);   // (8, 32, 3) = 768 CTAs
    gemm_qkv<<<qkvgrid, 256, PRJ_SMEM>>>(ih, il, wh, wl, bq, bk, bv, ph, pl);

    dim3 agrid(SS / 64, BB * HH);   // (32, 32) = 1024 CTAs, 4 per SM
    attn_bf<<<agrid, 128, ATT_SMEM>>>(ph, pl, ph + ME, pl + ME, ph + 2 * ME, pl + 2 * ME,
                                      mask, oh, ol);

    dim3 ogrid(EE / 128, (BB * SS) / 128);   // (8, 32)
    gemm_o<<<ogrid, 256, PRJ_SMEM>>>(oh, ol, wh + 3 * NE, wl + 3 * NE, bo, out);
}

// round 16
// speedup vs baseline: 1.3381x; 1.2416x over previous
#include <cuda_runtime.h>
#include <cstdint>

#define BB 2
#define SS 2048
#define EE 1024
#define HH 16
#define DHD 64
#define ME (4096 * 1024)
#define NE (1024 * 1024)

// ---------------------------------------------------------------------------
// PTX helpers (base-sm_103 features only)
// ---------------------------------------------------------------------------
__device__ __forceinline__ uint32_t smem_u32(const void* p) {
    uint32_t a;
    asm("{ .reg .u64 t; cvta.to.shared.u64 t, %1; cvt.u32.u64 %0, t; }" : "=r"(a) : "l"(p));
    return a;
}
__device__ __forceinline__ void ldsm4(uint32_t r[4], uint32_t a) {
    asm volatile("ldmatrix.sync.aligned.m8n8.x4.shared.b16 {%0,%1,%2,%3}, [%4];"
                 : "=r"(r[0]), "=r"(r[1]), "=r"(r[2]), "=r"(r[3]) : "r"(a));
}
__device__ __forceinline__ void ldsm4t(uint32_t r[4], uint32_t a) {
    asm volatile("ldmatrix.sync.aligned.m8n8.x4.trans.shared.b16 {%0,%1,%2,%3}, [%4];"
                 : "=r"(r[0]), "=r"(r[1]), "=r"(r[2]), "=r"(r[3]) : "r"(a));
}
__device__ __forceinline__ void mma_f16(float d[4], const uint32_t a[4], const uint32_t b[2]) {
    asm volatile("mma.sync.aligned.m16n8k16.row.col.f32.f16.f16.f32 "
                 "{%0,%1,%2,%3}, {%4,%5,%6,%7}, {%8,%9}, {%0,%1,%2,%3};"
                 : "+f"(d[0]), "+f"(d[1]), "+f"(d[2]), "+f"(d[3])
                 : "r"(a[0]), "r"(a[1]), "r"(a[2]), "r"(a[3]), "r"(b[0]), "r"(b[1]));
}
// fp32 pair -> single fp16x2
__device__ __forceinline__ uint32_t pack_h2(float2 v) {
    uint32_t r;
    asm("cvt.rn.f16x2.f32 %0, %1, %2;" : "=r"(r) : "f"(v.y), "f"(v.x));
    return r;
}
// fp32 pair -> fp16x2 hi + fp16x2 lo (x ~= hi + lo, residual ~u^2)
__device__ __forceinline__ void split2h(float2 v, uint32_t& hi, uint32_t& lo) {
    asm("cvt.rn.f16x2.f32 %0, %1, %2;" : "=r"(hi) : "f"(v.y), "f"(v.x));
    float h0, h1;
    asm("{\n\t.reg .f16 a, b;\n\tmov.b32 {a, b}, %2;\n\t"
        "cvt.f32.f16 %0, a;\n\tcvt.f32.f16 %1, b;\n\t}"
        : "=f"(h0), "=f"(h1) : "r"(hi));
    asm("cvt.rn.f16x2.f32 %0, %1, %2;" : "=r"(lo) : "f"(v.y - h1), "f"(v.x - h0));
}
__device__ __forceinline__ void cpa16(uint32_t dst, const void* src) {
    asm volatile("cp.async.cg.shared.global [%0], [%1], 16;" :: "r"(dst), "l"(src));
}
#define CPA_COMMIT() asm volatile("cp.async.commit_group;" ::: "memory")
#define CPA_WAIT0()  asm volatile("cp.async.wait_group 0;" ::: "memory")
#define CPA_WAIT1()  asm volatile("cp.async.wait_group 1;" ::: "memory")

// ---------------------------------------------------------------------------
// Global fp16 scratch (allocation-free)
// ---------------------------------------------------------------------------
__device__ uint16_t g_ia[3 * ME];                 // inputs q,k,v (single fp16)
__device__ uint16_t g_wh[4 * NE], g_wl[4 * NE];   // weights (fp16 hi/lo)
__device__ uint16_t g_ph[3 * ME], g_pl[2 * ME];   // Q single; K,V hi/lo (pl: K,V lo)
__device__ uint16_t g_oa[ME];                     // attention output (single fp16)

// ---------------------------------------------------------------------------
// Prep: inputs -> single fp16; weights -> fp16 hi/lo. One launch.
// ---------------------------------------------------------------------------
__global__ void split_all(const float* q, const float* k, const float* v,
                          const float* wq, const float* wk, const float* wv,
                          const float* wo,
                          uint16_t* ia, uint16_t* wh, uint16_t* wl)
{
    const int z = blockIdx.y;
    if (z < 3) {
        const float2* sp = (const float2*)(z == 0 ? q : z == 1 ? k : v);
        uint32_t* ap = (uint32_t*)(ia + (size_t)z * ME);
        const int n = ME / 2;
        for (int i = blockIdx.x * blockDim.x + threadIdx.x; i < n; i += gridDim.x * blockDim.x)
            ap[i] = pack_h2(sp[i]);
    } else {
        const int y = z - 3;
        const float2* sp = (const float2*)(y == 0 ? wq : y == 1 ? wk : y == 2 ? wv : wo);
        uint32_t* hp = (uint32_t*)(wh + (size_t)y * NE);
        uint32_t* lp = (uint32_t*)(wl + (size_t)y * NE);
        const int n = NE / 2;
        for (int i = blockIdx.x * blockDim.x + threadIdx.x; i < n; i += gridDim.x * blockDim.x) {
            uint32_t h, l;
            split2h(sp[i], h, l);
            hp[i] = h; lp[i] = l;
        }
    }
}

// ---------------------------------------------------------------------------
// Projection GEMM: C = (A*W^T + bias)*scale. A single fp16; W fp16 hi/lo.
// 2 MMAs per fragment pair. Tile 128x128, BK=64, 16 serial stages, 256 thr.
// smem: A[128][72] @0, Wh[128][72] @18432, Wl @36864  (54 KB, occ 2+).
// mode 0: fp32 out; 1: single fp16 out; 2: fp16 hi/lo out.
// ---------------------------------------------------------------------------
#define GP 72
#define GPB 144
#define PRJ_SMEM 55296

__device__ __forceinline__ void gemm_body(
    const uint16_t* __restrict__ Aa,
    const uint16_t* __restrict__ Wh, const uint16_t* __restrict__ Wl,
    const float* __restrict__ bias, float scale, int mode,
    float* __restrict__ Cf, uint16_t* __restrict__ Ch, uint16_t* __restrict__ Cl,
    char* sm, int bm, int bn)
{
    const uint32_t smb = smem_u32(sm);
    const int tid = threadIdx.x;
    const int w = tid >> 5, lane = tid & 31;
    const int m0 = (w & 1) * 64, n0 = (w >> 1) * 32;
    const int r8 = lane & 7, quad = lane >> 3;
    const int arow = (quad & 1) * 8 + r8, acol = (quad >> 1) * 8;
    const int brow = (quad >> 1) * 8 + r8, bcol = (quad & 1) * 8;

    float acc[4][4][4];
#pragma unroll
    for (int i = 0; i < 4; i++)
#pragma unroll
        for (int j = 0; j < 4; j++)
#pragma unroll
            for (int k = 0; k < 4; k++) acc[i][j][k] = 0.0f;

    for (int s = 0; s < 16; s++) {
        const int kk0 = s << 6;
        __syncthreads();
        // copy: 3 arrays x 128 rows x 8 chunks = 3072 over 256 thr = 12 iters
#pragma unroll
        for (int it = 0; it < 12; it++) {
            int idx = tid + it * 256;
            int a = idx >> 10, c = idx & 1023, row = c >> 3, cc = c & 7;
            const uint16_t* src;
            if (a == 0)      src = Aa + (size_t)(bm + row) * EE + kk0;
            else if (a == 1) src = Wh + (size_t)(bn + row) * EE + kk0;
            else             src = Wl + (size_t)(bn + row) * EE + kk0;
            cpa16(smb + a * 18432 + row * GPB + cc * 16, src + cc * 8);
        }
        CPA_COMMIT();
        CPA_WAIT0();
        __syncthreads();

#pragma unroll
        for (int kf = 0; kf < 4; kf++) {
            uint32_t bh[4][2], bl[4][2], t[4];
#pragma unroll
            for (int np = 0; np < 2; np++) {
                uint32_t boff = (uint32_t)((n0 + np * 16 + brow) * GP + kf * 16 + bcol) * 2;
                ldsm4(t, smb + 18432 + boff);
                bh[np * 2][0] = t[0]; bh[np * 2][1] = t[1];
                bh[np * 2 + 1][0] = t[2]; bh[np * 2 + 1][1] = t[3];
                ldsm4(t, smb + 36864 + boff);
                bl[np * 2][0] = t[0]; bl[np * 2][1] = t[1];
                bl[np * 2 + 1][0] = t[2]; bl[np * 2 + 1][1] = t[3];
            }
#pragma unroll
            for (int mf = 0; mf < 4; mf++) {
                uint32_t ah[4];
                uint32_t aoff = (uint32_t)((m0 + mf * 16 + arow) * GP + kf * 16 + acol) * 2;
                ldsm4(ah, smb + aoff);
#pragma unroll
                for (int nf = 0; nf < 4; nf++) {
                    mma_f16(acc[mf][nf], ah, bh[nf]);
                    mma_f16(acc[mf][nf], ah, bl[nf]);
                }
            }
        }
    }

    const int g2 = lane >> 2, t2 = (lane & 3) * 2;
#pragma unroll
    for (int mf = 0; mf < 4; mf++)
#pragma unroll
        for (int nf = 0; nf < 4; nf++) {
            int row0 = bm + m0 + mf * 16 + g2;
            int col = bn + n0 + nf * 8 + t2;
            float b0 = bias[col], b1 = bias[col + 1];
            float v0 = (acc[mf][nf][0] + b0) * scale, v1 = (acc[mf][nf][1] + b1) * scale;
            float v2 = (acc[mf][nf][2] + b0) * scale, v3 = (acc[mf][nf][3] + b1) * scale;
            size_t off = (size_t)row0 * EE + col;
            size_t off2 = off + (size_t)8 * EE;
            if (mode == 0) {
                *(float2*)(Cf + off)  = make_float2(v0, v1);
                *(float2*)(Cf + off2) = make_float2(v2, v3);
            } else if (mode == 1) {
                *(uint32_t*)(Ch + off)  = pack_h2(make_float2(v0, v1));
                *(uint32_t*)(Ch + off2) = pack_h2(make_float2(v2, v3));
            } else {
                uint32_t hi, lo;
                split2h(make_float2(v0, v1), hi, lo);
                *(uint32_t*)(Ch + off) = hi;
                *(uint32_t*)(Cl + off) = lo;
                split2h(make_float2(v2, v3), hi, lo);
                *(uint32_t*)(Ch + off2) = hi;
                *(uint32_t*)(Cl + off2) = lo;
            }
        }
}

__global__ __launch_bounds__(256, 2)
void gemm_qkv(const uint16_t* __restrict__ ia,
              const uint16_t* __restrict__ wh, const uint16_t* __restrict__ wl,
              const float* __restrict__ bq, const float* __restrict__ bk,
              const float* __restrict__ bv,
              uint16_t* __restrict__ ph, uint16_t* __restrict__ pl)
{
    extern __shared__ char sm[];
    const int z = blockIdx.z;
    const float* bias = (z == 0) ? bq : (z == 1 ? bk : bv);
    // Q (z=0): single fp16 -> ph[0..ME). K (z=1): hi -> ph[ME..2ME), lo -> pl[0..ME).
    // V (z=2): hi -> ph[2ME..3ME), lo -> pl[ME..2ME).
    uint16_t* ch = ph + (size_t)z * ME;
    uint16_t* cl = (z == 0) ? nullptr : pl + (size_t)(z - 1) * ME;
    gemm_body(ia + (size_t)z * ME,
              wh + (size_t)z * NE, wl + (size_t)z * NE,
              bias, (z == 0) ? 0.125f : 1.0f, (z == 0) ? 1 : 2,
              nullptr, ch, cl,
              sm, blockIdx.y * 128, blockIdx.x * 128);
}

__global__ __launch_bounds__(256, 2)
void gemm_o(const uint16_t* __restrict__ oa,
            const uint16_t* __restrict__ wh, const uint16_t* __restrict__ wl,
            const float* __restrict__ bo, float* __restrict__ out)
{
    extern __shared__ char sm[];
    gemm_body(oa, wh, wl, bo, 1.0f, 0, out, nullptr, nullptr,
              sm, blockIdx.y * 128, blockIdx.x * 128);
}

// ---------------------------------------------------------------------------
// Fused attention: q-tile 64, k-tile 32, 128 threads, 4 CTAs/SM, three
// rotating K/V buffers, one barrier per iteration. All fp16:
// gemm1 = Q(single) x K(hi+lo): 2 mmas. gemm2 = S(single) x V(hi+lo): 2 mmas.
// Q pre-scaled by 1/8. Output single fp16.
// ---------------------------------------------------------------------------
#define ATT_SMEM 55296

__device__ __forceinline__ void attn_issue_kv(
    uint32_t smb, int tid, uint32_t bufbase, size_t kb,
    const uint16_t* kh, const uint16_t* kl,
    const uint16_t* vh, const uint16_t* vl)
{
#pragma unroll
    for (int it = 0; it < 8; it++) {
        int idx = tid + it * 128;          // 0..1023
        int a = idx >> 8;                  // 0 KH, 1 KL, 2 VH, 3 VL (256 each)
        int c = idx & 255, row = c >> 3, cc = c & 7;
        const uint16_t* src =
            (a == 0 ? kh : a == 1 ? kl : a == 2 ? vh : vl) + kb + (size_t)row * EE + cc * 8;
        uint32_t dst = smb + bufbase + a * 4608 + row * GPB + cc * 16;
        cpa16(dst, src);
    }
}

__global__ __launch_bounds__(128, 4)
void attn_bf(const uint16_t* __restrict__ qa,
             const uint16_t* __restrict__ kh, const uint16_t* __restrict__ kl,
             const uint16_t* __restrict__ vh, const uint16_t* __restrict__ vl,
             const int* __restrict__ mask,
             uint16_t* __restrict__ oa)
{
    extern __shared__ char sm[];
    const uint32_t smb = smem_u32(sm);
    const int tid = threadIdx.x;
    const int q0 = blockIdx.x * 64;
    const int bh = blockIdx.y, b = bh >> 4, h = bh & 15, hoff = h * DHD;
    const int w = tid >> 5, lane = tid & 31;
    const int r8 = lane & 7, quad = lane >> 3;
    const int arow = (quad & 1) * 8 + r8, acol = (quad >> 1) * 8;
    const int brow = (quad >> 1) * 8 + r8, bcol = (quad & 1) * 8;
    const int g = lane >> 2, t2 = (lane & 3) * 2;

    const size_t rowbase = (size_t)b * SS;
    const size_t qb = (rowbase + q0) * EE + hoff;

    // prologue: Q tile (single fp16, 64x64) -> buffer 0; KV(0)->buf1; KV(1)->buf2
#pragma unroll
    for (int it = 0; it < 4; it++) {
        int idx = tid + it * 128;          // 0..511
        int row = idx >> 3, cc = idx & 7;
        cpa16(smb + row * GPB + cc * 16, qa + qb + (size_t)row * EE + cc * 8);
    }
    attn_issue_kv(smb, tid, 18432, rowbase * EE + hoff, kh, kl, vh, vl);
    CPA_COMMIT();                         // group0: Q + KV(0)
    attn_issue_kv(smb, tid, 36864, (rowbase + 32) * EE + hoff, kh, kl, vh, vl);
    CPA_COMMIT();                         // group1: KV(1)

    // wait group0, load Q fragments into registers permanently
    CPA_WAIT1();
    __syncthreads();
    uint32_t qf[4][4];
#pragma unroll
    for (int kf = 0; kf < 4; kf++) {
        uint32_t aoff = (uint32_t)((w * 16 + arow) * GP + kf * 16 + acol) * 2;
        ldsm4(qf[kf], smb + aoff);
    }

    float acc2[8][4];
#pragma unroll
    for (int j = 0; j < 8; j++)
#pragma unroll
        for (int k = 0; k < 4; k++) acc2[j][k] = 0.0f;

    const int mrow0 = (int)(rowbase + q0 + w * 16 + g);

    int jb = 1;                            // buffer index of current stage: (s+1)%3
    for (int ht = 0; ht < 64; ht++) {
        const int kg0 = ht * 32;
        const uint32_t cb = (uint32_t)jb * 18432u;
        int pj = jb + 2; if (pj >= 3) pj -= 3;
        const uint32_t pb = (uint32_t)pj * 18432u;

        // mask prefetch FIRST — independent of the pending K/V stage
        int2 mA[4], mB[4];
#pragma unroll
        for (int j = 0; j < 4; j++) {
            const int* mp = mask + (size_t)mrow0 * SS + kg0 + j * 8 + t2;
            mA[j] = *(const int2*)mp;
            mB[j] = *(const int2*)(mp + (size_t)8 * SS);
        }

        CPA_WAIT1();                       // KV(ht) complete (KV(ht+1) may be in flight)
        __syncthreads();                   // (a) data visible (b) compute(ht-1) done -> pb free

        if (ht + 2 < 64)
            attn_issue_kv(smb, tid, pb, (rowbase + (ht + 2) * 32) * EE + hoff, kh, kl, vh, vl);
        CPA_COMMIT();

        const uint32_t khs = smb + cb,        kls = khs + 4608;
        const uint32_t vhs = smb + cb + 9216, vls = vhs + 4608;

        // gemm1: S[16,32] = Q[16,64] * Khalf[32,64]^T   (fp16 2-term)
        float acc1[4][4];
#pragma unroll
        for (int j = 0; j < 4; j++)
#pragma unroll
            for (int k = 0; k < 4; k++) acc1[j][k] = 0.0f;

#pragma unroll
        for (int kf = 0; kf < 4; kf++) {
            uint32_t bhf[4][2], blf[4][2], t[4];
#pragma unroll
            for (int np = 0; np < 2; np++) {
                uint32_t boff = (uint32_t)((np * 16 + brow) * GP + kf * 16 + bcol) * 2;
                ldsm4(t, khs + boff);
                bhf[np * 2][0] = t[0]; bhf[np * 2][1] = t[1];
                bhf[np * 2 + 1][0] = t[2]; bhf[np * 2 + 1][1] = t[3];
                ldsm4(t, kls + boff);
                blf[np * 2][0] = t[0]; blf[np * 2][1] = t[1];
                blf[np * 2 + 1][0] = t[2]; blf[np * 2 + 1][1] = t[3];
            }
#pragma unroll
            for (int nf = 0; nf < 4; nf++) {
                mma_f16(acc1[nf], qf[kf], bhf[nf]);
                mma_f16(acc1[nf], qf[kf], blf[nf]);
            }
        }

        // mask in-register, convert S to single fp16 A-fragments
        uint32_t sf[2][4];
#pragma unroll
        for (int j = 0; j < 4; j++) {
            float v0 = mA[j].x ? acc1[j][0] : 1e-9f;
            float v1 = mA[j].y ? acc1[j][1] : 1e-9f;
            float v2 = mB[j].x ? acc1[j][2] : 1e-9f;
            float v3 = mB[j].y ? acc1[j][3] : 1e-9f;
            int kf = j >> 1, hi2 = (j & 1) * 2;
            sf[kf][hi2]     = pack_h2(make_float2(v0, v1));
            sf[kf][hi2 + 1] = pack_h2(make_float2(v2, v3));
        }

        // gemm2: O[16,64] += S[16,32] * Vhalf[32,64]   (fp16 2-term)
#pragma unroll
        for (int kf = 0; kf < 2; kf++) {
            uint32_t bhf[8][2], blf[8][2], t[4];
#pragma unroll
            for (int dp = 0; dp < 4; dp++) {
                uint32_t voff = (uint32_t)((kf * 16 + (quad & 1) * 8 + r8) * GP +
                                           dp * 16 + (quad >> 1) * 8) * 2;
                ldsm4t(t, vhs + voff);
                bhf[dp * 2][0] = t[0]; bhf[dp * 2][1] = t[1];
                bhf[dp * 2 + 1][0] = t[2]; bhf[dp * 2 + 1][1] = t[3];
                ldsm4t(t, vls + voff);
                blf[dp * 2][0] = t[0]; blf[dp * 2][1] = t[1];
                blf[dp * 2 + 1][0] = t[2]; blf[dp * 2 + 1][1] = t[3];
            }
#pragma unroll
            for (int nf = 0; nf < 8; nf++) {
                mma_f16(acc2[nf], sf[kf], bhf[nf]);
                mma_f16(acc2[nf], sf[kf], blf[nf]);
            }
        }
        // NO trailing barrier — next iteration's single sync guards the rotation.
        jb++; if (jb == 3) jb = 0;
    }

    // epilogue: O -> single fp16
#pragma unroll
    for (int j = 0; j < 8; j++) {
        int col = hoff + j * 8 + t2;
        size_t off = (size_t)mrow0 * EE + col;
        *(uint32_t*)(oa + off) = pack_h2(make_float2(acc2[j][0], acc2[j][1]));
        off += (size_t)8 * EE;
        *(uint32_t*)(oa + off) = pack_h2(make_float2(acc2[j][2], acc2[j][3]));
    }
}

// ---------------------------------------------------------------------------
extern "C" void kernel_launch(void* const* d_in, const int* in_sizes, int n_in,
                              void* d_out, int out_size)
{
    const float* query = (const float*)d_in[0];
    const float* key   = (const float*)d_in[1];
    const float* value = (const float*)d_in[2];
    const int*   mask  = (const int*)  d_in[3];
    const float* Wq    = (const float*)d_in[4];
    const float* bq    = (const float*)d_in[5];
    const float* Wk    = (const float*)d_in[6];
    const float* bk    = (const float*)d_in[7];
    const float* Wv    = (const float*)d_in[8];
    const float* bv    = (const float*)d_in[9];
    const float* Wo    = (const float*)d_in[10];
    const float* bo    = (const float*)d_in[11];
    float* out = (float*)d_out;

    uint16_t *ia, *wh, *wl, *ph, *pl, *oa;
    cudaGetSymbolAddress((void**)&ia, g_ia);
    cudaGetSymbolAddress((void**)&wh, g_wh);
    cudaGetSymbolAddress((void**)&wl, g_wl);
    cudaGetSymbolAddress((void**)&ph, g_ph);
    cudaGetSymbolAddress((void**)&pl, g_pl);
    cudaGetSymbolAddress((void**)&oa, g_oa);

    cudaFuncSetAttribute(gemm_qkv, cudaFuncAttributeMaxDynamicSharedMemorySize, PRJ_SMEM);
    cudaFuncSetAttribute(gemm_o,   cudaFuncAttributeMaxDynamicSharedMemorySize, PRJ_SMEM);
    cudaFuncSetAttribute(attn_bf,  cudaFuncAttributeMaxDynamicSharedMemorySize, ATT_SMEM);

    split_all<<<dim3(384, 7), 256>>>(query, key, value, Wq, Wk, Wv, Wo, ia, wh, wl);

    dim3 qkvgrid(EE / 128, (BB * SS) / 128, 3);   // (8, 32, 3) = 768 CTAs
    gemm_qkv<<<qkvgrid, 256, PRJ_SMEM>>>(ia, wh, wl, bq, bk, bv, ph, pl);

    // Q single @ph[0]; K hi @ph[ME], lo @pl[0]; V hi @ph[2ME], lo @pl[ME]
    dim3 agrid(SS / 64, BB * HH);   // (32, 32) = 1024 CTAs, 4 per SM
    attn_bf<<<agrid, 128, ATT_SMEM>>>(ph, ph + ME, pl, ph + 2 * ME, pl + ME,
                                      mask, oa);

    dim3 ogrid(EE / 128, (BB * SS) / 128);   // (8, 32)
    gemm_o<<<ogrid, 256, PRJ_SMEM>>>(oa, wh + 3 * NE, wl + 3 * NE, bo, out);
}

// round 17
// speedup vs baseline: 2.1595x; 1.6138x over previous
#include <cuda_runtime.h>
#include <cstdint>

#define BB 2
#define SS 2048
#define EE 1024
#define HH 16
#define DHD 64
#define ME (4096 * 1024)
#define NE (1024 * 1024)

// ---------------------------------------------------------------------------
// PTX helpers (base-sm_103 features only)
// ---------------------------------------------------------------------------
__device__ __forceinline__ uint32_t smem_u32(const void* p) {
    uint32_t a;
    asm("{ .reg .u64 t; cvta.to.shared.u64 t, %1; cvt.u32.u64 %0, t; }" : "=r"(a) : "l"(p));
    return a;
}
__device__ __forceinline__ void ldsm4(uint32_t r[4], uint32_t a) {
    asm volatile("ldmatrix.sync.aligned.m8n8.x4.shared.b16 {%0,%1,%2,%3}, [%4];"
                 : "=r"(r[0]), "=r"(r[1]), "=r"(r[2]), "=r"(r[3]) : "r"(a));
}
__device__ __forceinline__ void ldsm4t(uint32_t r[4], uint32_t a) {
    asm volatile("ldmatrix.sync.aligned.m8n8.x4.trans.shared.b16 {%0,%1,%2,%3}, [%4];"
                 : "=r"(r[0]), "=r"(r[1]), "=r"(r[2]), "=r"(r[3]) : "r"(a));
}
__device__ __forceinline__ void mma_f16(float d[4], const uint32_t a[4], const uint32_t b[2]) {
    asm volatile("mma.sync.aligned.m16n8k16.row.col.f32.f16.f16.f32 "
                 "{%0,%1,%2,%3}, {%4,%5,%6,%7}, {%8,%9}, {%0,%1,%2,%3};"
                 : "+f"(d[0]), "+f"(d[1]), "+f"(d[2]), "+f"(d[3])
                 : "r"(a[0]), "r"(a[1]), "r"(a[2]), "r"(a[3]), "r"(b[0]), "r"(b[1]));
}
// fp32 pair -> single fp16x2
__device__ __forceinline__ uint32_t pack_h2(float2 v) {
    uint32_t r;
    asm("cvt.rn.f16x2.f32 %0, %1, %2;" : "=r"(r) : "f"(v.y), "f"(v.x));
    return r;
}
__device__ __forceinline__ void cpa16(uint32_t dst, const void* src) {
    asm volatile("cp.async.cg.shared.global [%0], [%1], 16;" :: "r"(dst), "l"(src));
}
#define CPA_COMMIT() asm volatile("cp.async.commit_group;" ::: "memory")
#define CPA_WAIT0()  asm volatile("cp.async.wait_group 0;" ::: "memory")
#define CPA_WAIT1()  asm volatile("cp.async.wait_group 1;" ::: "memory")

// ---------------------------------------------------------------------------
// Global fp16 scratch (allocation-free) — all single fp16
// ---------------------------------------------------------------------------
__device__ uint16_t g_ia[3 * ME];     // inputs q,k,v
__device__ uint16_t g_wa[4 * NE];     // weights q,k,v,o
__device__ uint16_t g_pa[3 * ME];     // projected Q,K,V
__device__ uint16_t g_oa[ME];         // attention output

// ---------------------------------------------------------------------------
// Prep: everything -> single fp16. One launch, z selects tensor.
// ---------------------------------------------------------------------------
__global__ void split_all(const float* q, const float* k, const float* v,
                          const float* wq, const float* wk, const float* wv,
                          const float* wo,
                          uint16_t* ia, uint16_t* wa)
{
    const int z = blockIdx.y;
    const float2* sp;
    uint32_t* dp;
    int n;
    if (z < 3) {
        sp = (const float2*)(z == 0 ? q : z == 1 ? k : v);
        dp = (uint32_t*)(ia + (size_t)z * ME);
        n = ME / 2;
    } else {
        const int y = z - 3;
        sp = (const float2*)(y == 0 ? wq : y == 1 ? wk : y == 2 ? wv : wo);
        dp = (uint32_t*)(wa + (size_t)y * NE);
        n = NE / 2;
    }
    for (int i = blockIdx.x * blockDim.x + threadIdx.x; i < n; i += gridDim.x * blockDim.x)
        dp[i] = pack_h2(sp[i]);
}

// ---------------------------------------------------------------------------
// Projection GEMM: C = (A*W^T + bias)*scale. A, W single fp16 -> 1 MMA/pair.
// Tile 128x128, BK=64, 16 serial stages, 256 thr, occ 2.
// smem: A[128][72] @0 (18432), W[128][72] @18432. 36 KB.
// mode 0: fp32 out; 1: single fp16 out.
// ---------------------------------------------------------------------------
#define GP 72
#define GPB 144
#define PRJ_SMEM 36864

__device__ __forceinline__ void gemm_body(
    const uint16_t* __restrict__ Aa, const uint16_t* __restrict__ Wa,
    const float* __restrict__ bias, float scale, int mode,
    float* __restrict__ Cf, uint16_t* __restrict__ Ch,
    char* sm, int bm, int bn)
{
    const uint32_t smb = smem_u32(sm);
    const int tid = threadIdx.x;
    const int w = tid >> 5, lane = tid & 31;
    const int m0 = (w & 1) * 64, n0 = (w >> 1) * 32;
    const int r8 = lane & 7, quad = lane >> 3;
    const int arow = (quad & 1) * 8 + r8, acol = (quad >> 1) * 8;
    const int brow = (quad >> 1) * 8 + r8, bcol = (quad & 1) * 8;

    float acc[4][4][4];
#pragma unroll
    for (int i = 0; i < 4; i++)
#pragma unroll
        for (int j = 0; j < 4; j++)
#pragma unroll
            for (int k = 0; k < 4; k++) acc[i][j][k] = 0.0f;

    for (int s = 0; s < 16; s++) {
        const int kk0 = s << 6;
        __syncthreads();
        // copy: 2 arrays x 128 rows x 8 chunks = 2048 over 256 thr = 8 iters
#pragma unroll
        for (int it = 0; it < 8; it++) {
            int idx = tid + it * 256;
            int a = idx >> 10, c = idx & 1023, row = c >> 3, cc = c & 7;
            const uint16_t* src = (a ? Wa + (size_t)(bn + row) * EE
                                     : Aa + (size_t)(bm + row) * EE) + kk0 + cc * 8;
            cpa16(smb + a * 18432 + row * GPB + cc * 16, src);
        }
        CPA_COMMIT();
        CPA_WAIT0();
        __syncthreads();

#pragma unroll
        for (int kf = 0; kf < 4; kf++) {
            uint32_t bh[4][2], t[4];
#pragma unroll
            for (int np = 0; np < 2; np++) {
                uint32_t boff = (uint32_t)((n0 + np * 16 + brow) * GP + kf * 16 + bcol) * 2;
                ldsm4(t, smb + 18432 + boff);
                bh[np * 2][0] = t[0]; bh[np * 2][1] = t[1];
                bh[np * 2 + 1][0] = t[2]; bh[np * 2 + 1][1] = t[3];
            }
#pragma unroll
            for (int mf = 0; mf < 4; mf++) {
                uint32_t ah[4];
                uint32_t aoff = (uint32_t)((m0 + mf * 16 + arow) * GP + kf * 16 + acol) * 2;
                ldsm4(ah, smb + aoff);
#pragma unroll
                for (int nf = 0; nf < 4; nf++)
                    mma_f16(acc[mf][nf], ah, bh[nf]);
            }
        }
    }

    const int g2 = lane >> 2, t2 = (lane & 3) * 2;
#pragma unroll
    for (int mf = 0; mf < 4; mf++)
#pragma unroll
        for (int nf = 0; nf < 4; nf++) {
            int row0 = bm + m0 + mf * 16 + g2;
            int col = bn + n0 + nf * 8 + t2;
            float b0 = bias[col], b1 = bias[col + 1];
            float v0 = (acc[mf][nf][0] + b0) * scale, v1 = (acc[mf][nf][1] + b1) * scale;
            float v2 = (acc[mf][nf][2] + b0) * scale, v3 = (acc[mf][nf][3] + b1) * scale;
            size_t off = (size_t)row0 * EE + col;
            size_t off2 = off + (size_t)8 * EE;
            if (mode == 0) {
                *(float2*)(Cf + off)  = make_float2(v0, v1);
                *(float2*)(Cf + off2) = make_float2(v2, v3);
            } else {
                *(uint32_t*)(Ch + off)  = pack_h2(make_float2(v0, v1));
                *(uint32_t*)(Ch + off2) = pack_h2(make_float2(v2, v3));
            }
        }
}

__global__ __launch_bounds__(256, 2)
void gemm_qkv(const uint16_t* __restrict__ ia, const uint16_t* __restrict__ wa,
              const float* __restrict__ bq, const float* __restrict__ bk,
              const float* __restrict__ bv,
              uint16_t* __restrict__ pa)
{
    extern __shared__ char sm[];
    const int z = blockIdx.z;
    const float* bias = (z == 0) ? bq : (z == 1 ? bk : bv);
    gemm_body(ia + (size_t)z * ME, wa + (size_t)z * NE,
              bias, (z == 0) ? 0.125f : 1.0f, 1,
              nullptr, pa + (size_t)z * ME,
              sm, blockIdx.y * 128, blockIdx.x * 128);
}

__global__ __launch_bounds__(256, 2)
void gemm_o(const uint16_t* __restrict__ oa, const uint16_t* __restrict__ wa,
            const float* __restrict__ bo, float* __restrict__ out)
{
    extern __shared__ char sm[];
    gemm_body(oa, wa, bo, 1.0f, 0, out, nullptr,
              sm, blockIdx.y * 128, blockIdx.x * 128);
}

// ---------------------------------------------------------------------------
// Fused attention, all single fp16: q-tile 64, k-tile 32, 128 threads,
// 4+ CTAs/SM. Three rotating 9216B buffers (buf0 doubles as Q staging; Q
// lives in registers after prologue). One barrier per iteration.
// gemm1 = Q x K: 1 mma/pair. gemm2 = S x V: 1 mma/pair. Q pre-scaled 1/8.
// Stage layout: K[32][72] @ +0, V[32][72] @ +4608.
// ---------------------------------------------------------------------------
#define ATT_SMEM 27648

__device__ __forceinline__ void attn_issue_kv(
    uint32_t smb, int tid, uint32_t bufbase, size_t kb,
    const uint16_t* ka, const uint16_t* va)
{
#pragma unroll
    for (int it = 0; it < 4; it++) {
        int idx = tid + it * 128;          // 0..511
        int a = idx >> 8;                  // 0 K, 1 V (256 chunks each)
        int c = idx & 255, row = c >> 3, cc = c & 7;
        const uint16_t* src = (a ? va : ka) + kb + (size_t)row * EE + cc * 8;
        cpa16(smb + bufbase + a * 4608 + row * GPB + cc * 16, src);
    }
}

__global__ __launch_bounds__(128, 4)
void attn_f16(const uint16_t* __restrict__ qa,
              const uint16_t* __restrict__ ka, const uint16_t* __restrict__ va,
              const int* __restrict__ mask,
              uint16_t* __restrict__ oa)
{
    extern __shared__ char sm[];
    const uint32_t smb = smem_u32(sm);
    const int tid = threadIdx.x;
    const int q0 = blockIdx.x * 64;
    const int bh = blockIdx.y, b = bh >> 4, h = bh & 15, hoff = h * DHD;
    const int w = tid >> 5, lane = tid & 31;
    const int r8 = lane & 7, quad = lane >> 3;
    const int arow = (quad & 1) * 8 + r8, acol = (quad >> 1) * 8;
    const int brow = (quad >> 1) * 8 + r8, bcol = (quad & 1) * 8;
    const int g = lane >> 2, t2 = (lane & 3) * 2;

    const size_t rowbase = (size_t)b * SS;
    const size_t qb = (rowbase + q0) * EE + hoff;

    // prologue: Q tile (single fp16, 64x64 = 9216B) -> buffer 0
#pragma unroll
    for (int it = 0; it < 4; it++) {
        int idx = tid + it * 128;          // 0..511
        int row = idx >> 3, cc = idx & 7;
        cpa16(smb + row * GPB + cc * 16, qa + qb + (size_t)row * EE + cc * 8);
    }
    attn_issue_kv(smb, tid, 9216, rowbase * EE + hoff, ka, va);
    CPA_COMMIT();                         // group0: Q + KV(0)
    attn_issue_kv(smb, tid, 18432, (rowbase + 32) * EE + hoff, ka, va);
    CPA_COMMIT();                         // group1: KV(1)

    // wait group0, load Q fragments into registers permanently
    CPA_WAIT1();
    __syncthreads();
    uint32_t qf[4][4];
#pragma unroll
    for (int kf = 0; kf < 4; kf++) {
        uint32_t aoff = (uint32_t)((w * 16 + arow) * GP + kf * 16 + acol) * 2;
        ldsm4(qf[kf], smb + aoff);
    }

    float acc2[8][4];
#pragma unroll
    for (int j = 0; j < 8; j++)
#pragma unroll
        for (int k = 0; k < 4; k++) acc2[j][k] = 0.0f;

    const int mrow0 = (int)(rowbase + q0 + w * 16 + g);

    int jb = 1;                            // buffer of current stage: (s+1)%3
    for (int ht = 0; ht < 64; ht++) {
        const int kg0 = ht * 32;
        const uint32_t cb = (uint32_t)jb * 9216u;
        int pj = jb + 2; if (pj >= 3) pj -= 3;
        const uint32_t pb = (uint32_t)pj * 9216u;

        // mask prefetch FIRST — independent of the pending K/V stage
        int2 mA[4], mB[4];
#pragma unroll
        for (int j = 0; j < 4; j++) {
            const int* mp = mask + (size_t)mrow0 * SS + kg0 + j * 8 + t2;
            mA[j] = *(const int2*)mp;
            mB[j] = *(const int2*)(mp + (size_t)8 * SS);
        }

        CPA_WAIT1();                       // KV(ht) complete (KV(ht+1) in flight)
        __syncthreads();                   // data visible + compute(ht-1) done -> pb free

        if (ht + 2 < 64)
            attn_issue_kv(smb, tid, pb, (rowbase + (ht + 2) * 32) * EE + hoff, ka, va);
        CPA_COMMIT();

        const uint32_t khs = smb + cb;
        const uint32_t vhs = smb + cb + 4608;

        // gemm1: S[16,32] = Q[16,64] * Khalf[32,64]^T   (single fp16)
        float acc1[4][4];
#pragma unroll
        for (int j = 0; j < 4; j++)
#pragma unroll
            for (int k = 0; k < 4; k++) acc1[j][k] = 0.0f;

#pragma unroll
        for (int kf = 0; kf < 4; kf++) {
            uint32_t bf[4][2], t[4];
#pragma unroll
            for (int np = 0; np < 2; np++) {
                uint32_t boff = (uint32_t)((np * 16 + brow) * GP + kf * 16 + bcol) * 2;
                ldsm4(t, khs + boff);
                bf[np * 2][0] = t[0]; bf[np * 2][1] = t[1];
                bf[np * 2 + 1][0] = t[2]; bf[np * 2 + 1][1] = t[3];
            }
#pragma unroll
            for (int nf = 0; nf < 4; nf++)
                mma_f16(acc1[nf], qf[kf], bf[nf]);
        }

        // mask in-register, convert S to single fp16 A-fragments
        uint32_t sf[2][4];
#pragma unroll
        for (int j = 0; j < 4; j++) {
            float v0 = mA[j].x ? acc1[j][0] : 1e-9f;
            float v1 = mA[j].y ? acc1[j][1] : 1e-9f;
            float v2 = mB[j].x ? acc1[j][2] : 1e-9f;
            float v3 = mB[j].y ? acc1[j][3] : 1e-9f;
            int kf = j >> 1, hi2 = (j & 1) * 2;
            sf[kf][hi2]     = pack_h2(make_float2(v0, v1));
            sf[kf][hi2 + 1] = pack_h2(make_float2(v2, v3));
        }

        // gemm2: O[16,64] += S[16,32] * Vhalf[32,64]   (single fp16)
#pragma unroll
        for (int kf = 0; kf < 2; kf++) {
            uint32_t bf[8][2], t[4];
#pragma unroll
            for (int dp = 0; dp < 4; dp++) {
                uint32_t voff = (uint32_t)((kf * 16 + (quad & 1) * 8 + r8) * GP +
                                           dp * 16 + (quad >> 1) * 8) * 2;
                ldsm4t(t, vhs + voff);
                bf[dp * 2][0] = t[0]; bf[dp * 2][1] = t[1];
                bf[dp * 2 + 1][0] = t[2]; bf[dp * 2 + 1][1] = t[3];
            }
#pragma unroll
            for (int nf = 0; nf < 8; nf++)
                mma_f16(acc2[nf], sf[kf], bf[nf]);
        }
        // NO trailing barrier — next iteration's single sync guards the rotation.
        jb++; if (jb == 3) jb = 0;
    }

    // epilogue: O -> single fp16
#pragma unroll
    for (int j = 0; j < 8; j++) {
        int col = hoff + j * 8 + t2;
        size_t off = (size_t)mrow0 * EE + col;
        *(uint32_t*)(oa + off) = pack_h2(make_float2(acc2[j][0], acc2[j][1]));
        off += (size_t)8 * EE;
        *(uint32_t*)(oa + off) = pack_h2(make_float2(acc2[j][2], acc2[j][3]));
    }
}

// ---------------------------------------------------------------------------
extern "C" void kernel_launch(void* const* d_in, const int* in_sizes, int n_in,
                              void* d_out, int out_size)
{
    const float* query = (const float*)d_in[0];
    const float* key   = (const float*)d_in[1];
    const float* value = (const float*)d_in[2];
    const int*   mask  = (const int*)  d_in[3];
    const float* Wq    = (const float*)d_in[4];
    const float* bq    = (const float*)d_in[5];
    const float* Wk    = (const float*)d_in[6];
    const float* bk    = (const float*)d_in[7];
    const float* Wv    = (const float*)d_in[8];
    const float* bv    = (const float*)d_in[9];
    const float* Wo    = (const float*)d_in[10];
    const float* bo    = (const float*)d_in[11];
    float* out = (float*)d_out;

    uint16_t *ia, *wa, *pa, *oa;
    cudaGetSymbolAddress((void**)&ia, g_ia);
    cudaGetSymbolAddress((void**)&wa, g_wa);
    cudaGetSymbolAddress((void**)&pa, g_pa);
    cudaGetSymbolAddress((void**)&oa, g_oa);

    cudaFuncSetAttribute(gemm_qkv, cudaFuncAttributeMaxDynamicSharedMemorySize, PRJ_SMEM);
    cudaFuncSetAttribute(gemm_o,   cudaFuncAttributeMaxDynamicSharedMemorySize, PRJ_SMEM);
    cudaFuncSetAttribute(attn_f16, cudaFuncAttributeMaxDynamicSharedMemorySize, ATT_SMEM);

    split_all<<<dim3(384, 7), 256>>>(query, key, value, Wq, Wk, Wv, Wo, ia, wa);

    dim3 qkvgrid(EE / 128, (BB * SS) / 128, 3);   // (8, 32, 3) = 768 CTAs
    gemm_qkv<<<qkvgrid, 256, PRJ_SMEM>>>(ia, wa, bq, bk, bv, pa);

    dim3 agrid(SS / 64, BB * HH);   // (32, 32) = 1024 CTAs
    attn_f16<<<agrid, 128, ATT_SMEM>>>(pa, pa + ME, pa + 2 * ME, mask, oa);

    dim3 ogrid(EE / 128, (BB * SS) / 128);   // (8, 32)
    gemm_o<<<ogrid, 256, PRJ_SMEM>>>(oa, wa + 3 * NE, bo, out);
}